// round 1
// baseline (speedup 1.0000x reference)
#include <cuda_runtime.h>

#define HW   16384          // 128*128
#define Bn   8
#define Cn   10
#define NP   (Bn*HW)        // 131072 pixels total
#define NTH  256
#define NBL  (NP/NTH)       // 512 blocks

// Scratch (allocation-free: __device__ globals)
__device__ double g_acc1[40];                 // sums[20], sumsq[20] for BN1
__device__ double g_acc2[20];                 // sums[10], sumsq[10] for BN2
__device__ float  g_p1[40];                   // a1[20], b1[20]
__device__ float  g_p2[20];                   // a2[10], b2[10]
__device__ float  g_t1[Bn*2*Cn*HW];           // conv1 pre-BN output [b,20,hw]
__device__ float  g_y2[Bn*Cn*HW];             // conv2 pre-BN output [b,10,hw]

__device__ __forceinline__ float sigm(float x){ return 1.f/(1.f+__expf(-x)); }

__global__ void k_init(){
    int t = threadIdx.x;
    if (t < 40) g_acc1[t] = 0.0;
    if (t < 20) g_acc2[t] = 0.0;
}

// Pass A: node0 (ConvGRU on h0/f0), comp_att, t1 = W_r1 @ [f1, (h1+h2)*att], BN1 partial stats
__global__ void __launch_bounds__(NTH) k_passA(
    const float* __restrict__ f0, const float* __restrict__ h0,
    const float* __restrict__ f1, const float* __restrict__ h1, const float* __restrict__ h2,
    const float* __restrict__ W_att, const float* __restrict__ b_att,
    const float* __restrict__ W_r1,
    const float* __restrict__ Wg0, const float* __restrict__ bg0, const float* __restrict__ Wc0,
    float* __restrict__ node0, float* __restrict__ attOut)
{
    __shared__ float sWg0[40], sbg0[2], sWc0[200], sWatt[20], sWr1[400], sbatt;
    __shared__ float sAcc[40];
    int tid = threadIdx.x;
    for (int i=tid;i<40;i+=NTH)  sWg0[i]=Wg0[i];
    for (int i=tid;i<200;i+=NTH) sWc0[i]=Wc0[i];
    for (int i=tid;i<20;i+=NTH)  sWatt[i]=W_att[i];
    for (int i=tid;i<400;i+=NTH) sWr1[i]=W_r1[i];
    if (tid==0){ sbatt=b_att[0]; sbg0[0]=bg0[0]; sbg0[1]=bg0[1]; }
    if (tid<40) sAcc[tid]=0.f;
    __syncthreads();

    int idx = blockIdx.x*NTH + tid;
    int b = idx >> 14, p = idx & (HW-1);
    int base = b*Cn*HW + p;

    // ----- node0 = ConvGRU(x=h0, h=f0) -----
    float xv[Cn], hv[Cn];
    #pragma unroll
    for (int c=0;c<Cn;c++){ xv[c]=h0[base+c*HW]; hv[c]=f0[base+c*HW]; }
    float g0=sbg0[0], g1=sbg0[1];
    #pragma unroll
    for (int c=0;c<Cn;c++){
        g0 = fmaf(sWg0[c],    xv[c], fmaf(sWg0[10+c], hv[c], g0));
        g1 = fmaf(sWg0[20+c], xv[c], fmaf(sWg0[30+c], hv[c], g1));
    }
    float r = sigm(g0), u = sigm(g1);
    #pragma unroll
    for (int o=0;o<Cn;o++){
        float a=0.f;
        #pragma unroll
        for (int c=0;c<Cn;c++)
            a = fmaf(sWc0[o*20+c], xv[c], fmaf(sWc0[o*20+10+c], r*hv[c], a));
        node0[base+o*HW] = (1.f-u)*hv[o] + u*tanhf(a);
    }

    // ----- comp_att + t1 -----
    float sv[Cn], fv[Cn];
    float ga = sbatt;
    #pragma unroll
    for (int c=0;c<Cn;c++){
        float a1v=h1[base+c*HW], a2v=h2[base+c*HW];
        ga = fmaf(sWatt[c], a1v, fmaf(sWatt[10+c], a2v, ga));
        sv[c]=a1v+a2v;
    }
    float att = sigm(ga);
    attOut[b*HW+p] = att;
    #pragma unroll
    for (int c=0;c<Cn;c++){ sv[c]*=att; fv[c]=f1[base+c*HW]; }

    int lane = tid & 31;
    #pragma unroll
    for (int o=0;o<2*Cn;o++){
        float t=0.f;
        #pragma unroll
        for (int c=0;c<Cn;c++)
            t = fmaf(sWr1[o*20+c], fv[c], fmaf(sWr1[o*20+10+c], sv[c], t));
        g_t1[(b*2*Cn+o)*HW + p] = t;
        float s=t, q=t*t;
        #pragma unroll
        for (int off=16;off;off>>=1){
            s += __shfl_xor_sync(0xffffffffu,s,off);
            q += __shfl_xor_sync(0xffffffffu,q,off);
        }
        if (lane==0){ atomicAdd(&sAcc[o],s); atomicAdd(&sAcc[20+o],q); }
    }
    __syncthreads();
    if (tid<40) atomicAdd(&g_acc1[tid], (double)sAcc[tid]);
}

__global__ void k_stats1(const float* __restrict__ gamma, const float* __restrict__ beta){
    int t=threadIdx.x;
    if (t<20){
        double m = g_acc1[t]    * (1.0/131072.0);
        double v = g_acc1[20+t] * (1.0/131072.0) - m*m;
        float a = gamma[t] * rsqrtf((float)v + 1e-5f);
        g_p1[t]    = a;
        g_p1[20+t] = beta[t] - (float)(a*m);
    }
}

// Pass B: x1 = relu(bn1(t1)), y2 = W_r2 @ x1, BN2 partial stats
__global__ void __launch_bounds__(NTH) k_passB(const float* __restrict__ W_r2)
{
    __shared__ float sW[200], sP[40], sAcc[20];
    int tid = threadIdx.x;
    for (int i=tid;i<200;i+=NTH) sW[i]=W_r2[i];
    if (tid<40) sP[tid]=g_p1[tid];
    if (tid<20) sAcc[tid]=0.f;
    __syncthreads();

    int idx = blockIdx.x*NTH + tid;
    int b = idx >> 14, p = idx & (HW-1);

    float x1[20];
    #pragma unroll
    for (int o=0;o<20;o++){
        float t = g_t1[(b*20+o)*HW+p];
        x1[o] = fmaxf(fmaf(sP[o], t, sP[20+o]), 0.f);
    }
    int lane = tid & 31;
    #pragma unroll
    for (int o=0;o<10;o++){
        float y=0.f;
        #pragma unroll
        for (int c=0;c<20;c++) y = fmaf(sW[o*20+c], x1[c], y);
        g_y2[(b*10+o)*HW+p] = y;
        float s=y, q=y*y;
        #pragma unroll
        for (int off=16;off;off>>=1){
            s += __shfl_xor_sync(0xffffffffu,s,off);
            q += __shfl_xor_sync(0xffffffffu,q,off);
        }
        if (lane==0){ atomicAdd(&sAcc[o],s); atomicAdd(&sAcc[10+o],q); }
    }
    __syncthreads();
    if (tid<20) atomicAdd(&g_acc2[tid], (double)sAcc[tid]);
}

__global__ void k_stats2(const float* __restrict__ gamma, const float* __restrict__ beta){
    int t=threadIdx.x;
    if (t<10){
        double m = g_acc2[t]    * (1.0/131072.0);
        double v = g_acc2[10+t] * (1.0/131072.0) - m*m;
        float a = gamma[t] * rsqrtf((float)v + 1e-5f);
        g_p2[t]    = a;
        g_p2[10+t] = beta[t] - (float)(a*m);
    }
}

// Pass C: comp_full = relu(bn2(y2)), node1 = ConvGRU(x=comp_full, h=f1)
__global__ void __launch_bounds__(NTH) k_passC(
    const float* __restrict__ f1,
    const float* __restrict__ Wg1, const float* __restrict__ bg1, const float* __restrict__ Wc1,
    float* __restrict__ node1)
{
    __shared__ float sWg[40], sbg[2], sWc[200], sP[20];
    int tid = threadIdx.x;
    for (int i=tid;i<40;i+=NTH)  sWg[i]=Wg1[i];
    for (int i=tid;i<200;i+=NTH) sWc[i]=Wc1[i];
    if (tid<20) sP[tid]=g_p2[tid];
    if (tid==0){ sbg[0]=bg1[0]; sbg[1]=bg1[1]; }
    __syncthreads();

    int idx = blockIdx.x*NTH + tid;
    int b = idx >> 14, p = idx & (HW-1);
    int base = b*Cn*HW + p;

    float cf[Cn], fv[Cn];
    #pragma unroll
    for (int o=0;o<Cn;o++){
        float y = g_y2[(b*Cn+o)*HW+p];
        cf[o] = fmaxf(fmaf(sP[o], y, sP[10+o]), 0.f);
    }
    #pragma unroll
    for (int c=0;c<Cn;c++) fv[c]=f1[base+c*HW];

    float g0=sbg[0], g1=sbg[1];
    #pragma unroll
    for (int c=0;c<Cn;c++){
        g0 = fmaf(sWg[c],    cf[c], fmaf(sWg[10+c], fv[c], g0));
        g1 = fmaf(sWg[20+c], cf[c], fmaf(sWg[30+c], fv[c], g1));
    }
    float r = sigm(g0), u = sigm(g1);
    #pragma unroll
    for (int o=0;o<Cn;o++){
        float a=0.f;
        #pragma unroll
        for (int c=0;c<Cn;c++)
            a = fmaf(sWc[o*20+c], cf[c], fmaf(sWc[o*20+10+c], r*fv[c], a));
        node1[base+o*HW] = (1.f-u)*fv[o] + u*tanhf(a);
    }
}

extern "C" void kernel_launch(void* const* d_in, const int* in_sizes, int n_in,
                              void* d_out, int out_size)
{
    const float* f0    = (const float*)d_in[0];
    const float* f1    = (const float*)d_in[1];
    const float* h0    = (const float*)d_in[2];
    const float* h1    = (const float*)d_in[3];
    const float* h2    = (const float*)d_in[4];
    const float* W_att = (const float*)d_in[5];
    const float* b_att = (const float*)d_in[6];
    const float* W_r1  = (const float*)d_in[7];
    const float* g_r1  = (const float*)d_in[8];
    const float* be_r1 = (const float*)d_in[9];
    const float* W_r2  = (const float*)d_in[10];
    const float* g_r2  = (const float*)d_in[11];
    const float* be_r2 = (const float*)d_in[12];
    const float* Wg0   = (const float*)d_in[13];
    const float* bg0   = (const float*)d_in[14];
    const float* Wc0   = (const float*)d_in[15];
    const float* Wg1   = (const float*)d_in[16];
    const float* bg1   = (const float*)d_in[17];
    const float* Wc1   = (const float*)d_in[18];

    float* out   = (float*)d_out;
    float* node0 = out;                      // [8,10,128,128]
    float* node1 = out + Bn*Cn*HW;           // [8,10,128,128]
    float* att   = out + 2*Bn*Cn*HW;         // [8,1,128,128]

    k_init<<<1, 64>>>();
    k_passA<<<NBL, NTH>>>(f0, h0, f1, h1, h2, W_att, b_att, W_r1,
                          Wg0, bg0, Wc0, node0, att);
    k_stats1<<<1, 32>>>(g_r1, be_r1);
    k_passB<<<NBL, NTH>>>(W_r2);
    k_stats2<<<1, 32>>>(g_r2, be_r2);
    k_passC<<<NBL, NTH>>>(f1, Wg1, bg1, Wc1, node1);
}